// round 10
// baseline (speedup 1.0000x reference)
#include <cuda_runtime.h>
#include <cuda_bf16.h>
#include <cstdint>

#define N_NODES 100000
#define N_EDGES 1600000
#define D 128
#define N_PANELS (N_NODES / 16)          // 6250, exact
#define SCAN_BLK 1024
#define N_SCAN_BLOCKS ((N_NODES + SCAN_BLK - 1) / SCAN_BLK)   // 98

// ---------------------------------------------------------------------------
// Device scratch
// ---------------------------------------------------------------------------
__device__ int    g_cnt [N_NODES];
__device__ int    g_cur [N_NODES];
__device__ int    g_off [N_NODES + 1];
__device__ int    g_bsum[128];
__device__ float4 g_edata[N_EDGES];                  // {eid, src, w, pad}
// A in mma-fragment layout: [panel][ks(16)][lane(32)] -> uint4 {a0,a1,a2,a3}
__device__ uint4  g_xhi4[(size_t)N_PANELS * 512];
__device__ uint4  g_xlo4[(size_t)N_PANELS * 512];
// W in fragment layout: [npp(8)][ks(16)][lane(32)][word(4)] (uint32 words)
__device__ uint32_t g_whi32[16384];
__device__ uint32_t g_wlo32[16384];

// ---------------------------------------------------------------------------
// helpers
// ---------------------------------------------------------------------------
typedef unsigned long long u64;

__device__ __forceinline__ uint32_t bfpair(float a, float b) {
    __nv_bfloat162 t = __floats2bfloat162_rn(a, b);
    return *reinterpret_cast<uint32_t*>(&t);
}
__device__ __forceinline__ void mma_bf16(float* d, const uint32_t* a,
                                         uint32_t b0, uint32_t b1) {
    asm volatile(
        "mma.sync.aligned.m16n8k16.row.col.f32.bf16.bf16.f32 "
        "{%0,%1,%2,%3}, {%4,%5,%6,%7}, {%8,%9}, {%0,%1,%2,%3};"
        : "+f"(d[0]), "+f"(d[1]), "+f"(d[2]), "+f"(d[3])
        : "r"(a[0]), "r"(a[1]), "r"(a[2]), "r"(a[3]), "r"(b0), "r"(b1));
}

// L2 cache-policy creation (once per thread)
__device__ __forceinline__ u64 pol_evict_first() {
    u64 p;
    asm("createpolicy.fractional.L2::evict_first.b64 %0, 1.0;" : "=l"(p));
    return p;
}
__device__ __forceinline__ u64 pol_evict_last() {
    u64 p;
    asm("createpolicy.fractional.L2::evict_last.b64 %0, 1.0;" : "=l"(p));
    return p;
}
// policy-hinted 128-bit loads
__device__ __forceinline__ float4 ld_pol(const float4* p, u64 pol) {
    float4 v;
    asm volatile("ld.global.nc.L2::cache_hint.v4.f32 {%0,%1,%2,%3}, [%4], %5;"
                 : "=f"(v.x), "=f"(v.y), "=f"(v.z), "=f"(v.w) : "l"(p), "l"(pol));
    return v;
}
__device__ __forceinline__ uint4 ld_pol_u4(const uint4* p, u64 pol) {
    uint4 v;
    asm volatile("ld.global.nc.L2::cache_hint.v4.u32 {%0,%1,%2,%3}, [%4], %5;"
                 : "=r"(v.x), "=r"(v.y), "=r"(v.z), "=r"(v.w) : "l"(p), "l"(pol));
    return v;
}

// ---------------------------------------------------------------------------
// Setup kernels
// ---------------------------------------------------------------------------
__global__ void k_zero() {
    int i = blockIdx.x * blockDim.x + threadIdx.x;
    if (i < N_NODES) { g_cnt[i] = 0; g_cur[i] = 0; }
}

__global__ __launch_bounds__(256) void k_hist(const int* __restrict__ dst) {
    int e = blockIdx.x * blockDim.x + threadIdx.x;
    if (e < N_EDGES) atomicAdd(&g_cnt[dst[e]], 1);
}

__global__ __launch_bounds__(SCAN_BLK) void k_scan1() {
    __shared__ int warp_pfx[32];
    const int tid = threadIdx.x;
    const int i   = blockIdx.x * SCAN_BLK + tid;
    const int v   = (i < N_NODES) ? g_cnt[i] : 0;

    int x = v;
#pragma unroll
    for (int o = 1; o < 32; o <<= 1) {
        int y = __shfl_up_sync(0xffffffffu, x, o);
        if ((tid & 31) >= o) x += y;
    }
    if ((tid & 31) == 31) warp_pfx[tid >> 5] = x;
    __syncthreads();
    if (tid < 32) {
        int t = warp_pfx[tid];
        int s = t;
#pragma unroll
        for (int o = 1; o < 32; o <<= 1) {
            int y = __shfl_up_sync(0xffffffffu, s, o);
            if (tid >= o) s += y;
        }
        warp_pfx[tid] = s - t;
        if (tid == 31) g_bsum[blockIdx.x] = s;
    }
    __syncthreads();
    if (i < N_NODES) g_off[i] = (x - v) + warp_pfx[tid >> 5];
}

__global__ __launch_bounds__(128) void k_scan2() {
    __shared__ int s[128];
    const int tid = threadIdx.x;
    const int v = (tid < N_SCAN_BLOCKS) ? g_bsum[tid] : 0;
    s[tid] = v;
    __syncthreads();
#pragma unroll
    for (int o = 1; o < 128; o <<= 1) {
        int y = (tid >= o) ? s[tid - o] : 0;
        __syncthreads();
        s[tid] += y;
        __syncthreads();
    }
    if (tid < N_SCAN_BLOCKS) g_bsum[tid] = s[tid] - v;
}

__global__ void k_scan3() {
    int i = blockIdx.x * blockDim.x + threadIdx.x;
    if (i < N_NODES) g_off[i] += g_bsum[i >> 10];
    if (i == 0) g_off[N_NODES] = N_EDGES;
}

__global__ __launch_bounds__(256) void k_perm(const int* __restrict__ src,
                                              const int* __restrict__ dst,
                                              const float* __restrict__ ew) {
    int e = blockIdx.x * blockDim.x + threadIdx.x;
    if (e >= N_EDGES) return;
    const int d   = dst[e];
    const int pos = g_off[d] + atomicAdd(&g_cur[d], 1);
    g_edata[pos] = make_float4(__int_as_float(e), __int_as_float(src[e]),
                               __ldg(ew + e), 0.f);
}

// W -> bf16 hi/lo directly in B-fragment layout
__global__ __launch_bounds__(256) void k_wsplit(const float* __restrict__ Wn,
                                                const float* __restrict__ We) {
    const int idx = blockIdx.x * blockDim.x + threadIdx.x;  // 0..16383
    if (idx >= 16384) return;
    const int e    = idx >> 2;
    const int word = idx & 3;
    const int npp  = e >> 9;          // /512
    const int rem  = e & 511;
    const int ks   = rem >> 5;
    const int lane = rem & 31;
    const int gid  = lane >> 2;
    const int tig  = lane & 3;
    const int col  = npp * 16 + (word >> 1) * 8 + gid;
    const int k    = ks * 16 + (word & 1) * 8 + tig * 2;

    float v0, v1;
    if (k < 128) { v0 = __ldg(Wn + col * 128 + k);       v1 = __ldg(Wn + col * 128 + k + 1); }
    else         { v0 = __ldg(We + col * 128 + k - 128); v1 = __ldg(We + col * 128 + k - 127); }

    const float h0 = __bfloat162float(__float2bfloat16(v0));
    const float h1 = __bfloat162float(__float2bfloat16(v1));
    g_whi32[idx] = bfpair(h0, h1);
    g_wlo32[idx] = bfpair(v0 - h0, v1 - h1);
}

// ---------------------------------------------------------------------------
// Gather: 512 threads = 16 warps = 1 panel (16 nodes). Warp w gathers node
// blockIdx.x*16+w; smem transpose into A-fragment layout. Edge metadata is
// software-pipelined; efeat/edata evict_first, nfeat evict_last.
// ---------------------------------------------------------------------------
__global__ __launch_bounds__(512) void k_gather(const float* __restrict__ nfeat,
                                                const float* __restrict__ efeat) {
    __shared__ uint32_t hi32[16][132];
    __shared__ uint32_t lo32[16][132];

    const u64 polF = pol_evict_first();
    const u64 polL = pol_evict_last();

    const int tid  = threadIdx.x;
    const int w    = tid >> 5;
    const int lane = tid & 31;
    const int pan  = blockIdx.x;
    const int n    = pan * 16 + w;            // always < N_NODES

    const int beg = __ldg(g_off + n);
    const int end = __ldg(g_off + n + 1);

    float4 accn = make_float4(0.f, 0.f, 0.f, 0.f);
    float4 acce = make_float4(0.f, 0.f, 0.f, 0.f);

    int i = beg;
    if (i + 3 < end) {
        float4 p0 = ld_pol(g_edata + i + 0, polF);
        float4 p1 = ld_pol(g_edata + i + 1, polF);
        float4 p2 = ld_pol(g_edata + i + 2, polF);
        float4 p3 = ld_pol(g_edata + i + 3, polF);
        for (;;) {
            const int e0 = __float_as_int(p0.x), s0 = __float_as_int(p0.y);
            const int e1 = __float_as_int(p1.x), s1 = __float_as_int(p1.y);
            const int e2 = __float_as_int(p2.x), s2 = __float_as_int(p2.y);
            const int e3 = __float_as_int(p3.x), s3 = __float_as_int(p3.y);
            const float w0 = p0.z, w1 = p1.z, w2 = p2.z, w3 = p3.z;

            const float4 f0 = ld_pol(reinterpret_cast<const float4*>(efeat + (size_t)e0 * D) + lane, polF);
            const float4 f1 = ld_pol(reinterpret_cast<const float4*>(efeat + (size_t)e1 * D) + lane, polF);
            const float4 f2 = ld_pol(reinterpret_cast<const float4*>(efeat + (size_t)e2 * D) + lane, polF);
            const float4 f3 = ld_pol(reinterpret_cast<const float4*>(efeat + (size_t)e3 * D) + lane, polF);
            const float4 m0 = ld_pol(reinterpret_cast<const float4*>(nfeat + (size_t)s0 * D) + lane, polL);
            const float4 m1 = ld_pol(reinterpret_cast<const float4*>(nfeat + (size_t)s1 * D) + lane, polL);
            const float4 m2 = ld_pol(reinterpret_cast<const float4*>(nfeat + (size_t)s2 * D) + lane, polL);
            const float4 m3 = ld_pol(reinterpret_cast<const float4*>(nfeat + (size_t)s3 * D) + lane, polL);

            const int ni = i + 4;
            const bool more = ni + 3 < end;
            float4 q0, q1, q2, q3;
            if (more) {
                q0 = ld_pol(g_edata + ni + 0, polF);
                q1 = ld_pol(g_edata + ni + 1, polF);
                q2 = ld_pol(g_edata + ni + 2, polF);
                q3 = ld_pol(g_edata + ni + 3, polF);
            }

            acce.x += (f0.x + f1.x) + (f2.x + f3.x);
            acce.y += (f0.y + f1.y) + (f2.y + f3.y);
            acce.z += (f0.z + f1.z) + (f2.z + f3.z);
            acce.w += (f0.w + f1.w) + (f2.w + f3.w);
            accn.x += (w0 * m0.x + w1 * m1.x) + (w2 * m2.x + w3 * m3.x);
            accn.y += (w0 * m0.y + w1 * m1.y) + (w2 * m2.y + w3 * m3.y);
            accn.z += (w0 * m0.z + w1 * m1.z) + (w2 * m2.z + w3 * m3.z);
            accn.w += (w0 * m0.w + w1 * m1.w) + (w2 * m2.w + w3 * m3.w);

            i = ni;
            if (!more) break;
            p0 = q0; p1 = q1; p2 = q2; p3 = q3;
        }
    }
    for (; i < end; i++) {
        const float4 p = __ldg(g_edata + i);
        const int e = __float_as_int(p.x), s = __float_as_int(p.y);
        const float wt = p.z;
        const float4 f  = ld_pol(reinterpret_cast<const float4*>(efeat + (size_t)e * D) + lane, polF);
        const float4 mm = ld_pol(reinterpret_cast<const float4*>(nfeat + (size_t)s * D) + lane, polL);
        acce.x += f.x; acce.y += f.y; acce.z += f.z; acce.w += f.w;
        accn.x += wt * mm.x; accn.y += wt * mm.y; accn.z += wt * mm.z; accn.w += wt * mm.w;
    }

    const float deg = (float)(end - beg);
    const float rd1 = 1.f / (deg + 1.f);
    const float rd2 = 1.f / fmaxf(deg, 1.f);

    const float4 self = ld_pol(reinterpret_cast<const float4*>(nfeat + (size_t)n * D) + lane, polL);
    float x1[4], x2[4];
    x1[0] = (accn.x + 2.f * self.x) * rd1;
    x1[1] = (accn.y + 2.f * self.y) * rd1;
    x1[2] = (accn.z + 2.f * self.z) * rd1;
    x1[3] = (accn.w + 2.f * self.w) * rd1;
    x2[0] = acce.x * rd2; x2[1] = acce.y * rd2;
    x2[2] = acce.z * rd2; x2[3] = acce.w * rd2;

    float h1[4], h2[4];
#pragma unroll
    for (int j = 0; j < 4; j++) {
        h1[j] = __bfloat162float(__float2bfloat16(x1[j]));
        h2[j] = __bfloat162float(__float2bfloat16(x2[j]));
    }
    {
        uint2 a, b;
        a.x = bfpair(h1[0], h1[1]);             a.y = bfpair(h1[2], h1[3]);
        b.x = bfpair(x1[0]-h1[0], x1[1]-h1[1]); b.y = bfpair(x1[2]-h1[2], x1[3]-h1[3]);
        *reinterpret_cast<uint2*>(&hi32[w][2 * lane]) = a;
        *reinterpret_cast<uint2*>(&lo32[w][2 * lane]) = b;
    }
    {
        uint2 a, b;
        a.x = bfpair(h2[0], h2[1]);             a.y = bfpair(h2[2], h2[3]);
        b.x = bfpair(x2[0]-h2[0], x2[1]-h2[1]); b.y = bfpair(x2[2]-h2[2], x2[3]-h2[3]);
        *reinterpret_cast<uint2*>(&hi32[w][64 + 2 * lane]) = a;
        *reinterpret_cast<uint2*>(&lo32[w][64 + 2 * lane]) = b;
    }
    __syncthreads();

    {
        const int ks  = w;
        const int gid = lane >> 2;
        const int tig = lane & 3;
        uint4 vh, vl;
        vh.x = hi32[gid    ][ks * 8 + tig];
        vh.y = hi32[gid + 8][ks * 8 + tig];
        vh.z = hi32[gid    ][ks * 8 + 4 + tig];
        vh.w = hi32[gid + 8][ks * 8 + 4 + tig];
        vl.x = lo32[gid    ][ks * 8 + tig];
        vl.y = lo32[gid + 8][ks * 8 + tig];
        vl.z = lo32[gid    ][ks * 8 + 4 + tig];
        vl.w = lo32[gid + 8][ks * 8 + 4 + tig];
        const size_t eidx = ((size_t)pan * 16 + ks) * 32 + lane;
        g_xhi4[eidx] = vh;
        g_xlo4[eidx] = vl;
    }
}

// ---------------------------------------------------------------------------
// HMMA GEMM with fragment-layout operands. 256 threads = 8 warps.
// Block: 128 rows (8 panels) x 128 cols. Warp tile 32(M) x 64(N).
// A fragments streamed with evict_first (read exactly once).
// ---------------------------------------------------------------------------
__global__ __launch_bounds__(256) void k_mgemm(const float* __restrict__ bn,
                                               const float* __restrict__ be,
                                               float* __restrict__ out) {
    const u64 polF = pol_evict_first();

    const int bx   = blockIdx.x;
    const int tid  = threadIdx.x;
    const int w    = tid >> 5;
    const int lane = tid & 31;
    const int gid  = lane >> 2;
    const int tig  = lane & 3;
    const int warp_m = (w & 3) * 32;
    const int warp_n = (w >> 2) * 64;
    const int n0   = bx * 128;
    const int nppb = (w >> 2) * 4;

    float acc[2][8][4];
#pragma unroll
    for (int mt = 0; mt < 2; mt++)
#pragma unroll
        for (int nt = 0; nt < 8; nt++)
#pragma unroll
            for (int j = 0; j < 4; j++) acc[mt][nt][j] = 0.f;

    int  pan[2];
    bool pv[2];
#pragma unroll
    for (int mt = 0; mt < 2; mt++) {
        pan[mt] = bx * 8 + (w & 3) * 2 + mt;
        pv[mt]  = pan[mt] < N_PANELS;
    }

    const uint4* W4base[2] = { reinterpret_cast<const uint4*>(g_whi32),
                               reinterpret_cast<const uint4*>(g_wlo32) };

#pragma unroll 1
    for (int pass = 0; pass < 3; pass++) {
        const uint4* A4 = (pass == 2) ? g_xlo4 : g_xhi4;
        const uint4* B4 = W4base[(pass == 1) ? 1 : 0];

#pragma unroll 4
        for (int ks = 0; ks < 16; ks++) {
            uint4 a4[2];
#pragma unroll
            for (int mt = 0; mt < 2; mt++) {
                a4[mt] = make_uint4(0, 0, 0, 0);
                if (pv[mt])
                    a4[mt] = ld_pol_u4(A4 + ((size_t)(pan[mt] * 16 + ks) * 32 + lane), polF);
            }
#pragma unroll
            for (int npq = 0; npq < 4; npq++) {
                const uint4 b4 = __ldg(B4 + (((nppb + npq) * 16 + ks) * 32 + lane));
#pragma unroll
                for (int mt = 0; mt < 2; mt++) {
                    mma_bf16(acc[mt][npq * 2 + 0],
                             reinterpret_cast<const uint32_t*>(&a4[mt]), b4.x, b4.y);
                    mma_bf16(acc[mt][npq * 2 + 1],
                             reinterpret_cast<const uint32_t*>(&a4[mt]), b4.z, b4.w);
                }
            }
        }
    }

#pragma unroll
    for (int mt = 0; mt < 2; mt++) {
        const int rA = n0 + warp_m + mt * 16 + gid;
        const int rB = rA + 8;
        const bool vA = rA < N_NODES;
        const bool vB = rB < N_NODES;
        float fA = 0.f, fB = 0.f;
        if (vA) fA = (__ldg(g_off + rA + 1) - __ldg(g_off + rA) > 0) ? 1.f : 0.f;
        if (vB) fB = (__ldg(g_off + rB + 1) - __ldg(g_off + rB) > 0) ? 1.f : 0.f;

#pragma unroll
        for (int nt = 0; nt < 8; nt++) {
            const int col = warp_n + nt * 8 + tig * 2;
            const float2 bnv = __ldg(reinterpret_cast<const float2*>(bn + col));
            const float2 bev = __ldg(reinterpret_cast<const float2*>(be + col));
            if (vA) {
                float2 o;
                o.x = acc[mt][nt][0] + bnv.x + fA * bev.x;
                o.y = acc[mt][nt][1] + bnv.y + fA * bev.y;
                *reinterpret_cast<float2*>(out + (size_t)rA * 128 + col) = o;
            }
            if (vB) {
                float2 o;
                o.x = acc[mt][nt][2] + bnv.x + fB * bev.x;
                o.y = acc[mt][nt][3] + bnv.y + fB * bev.y;
                *reinterpret_cast<float2*>(out + (size_t)rB * 128 + col) = o;
            }
        }
    }
}

// ---------------------------------------------------------------------------
extern "C" void kernel_launch(void* const* d_in, const int* in_sizes, int n_in,
                              void* d_out, int out_size) {
    const float* nfeat = (const float*)d_in[0];
    const float* efeat = (const float*)d_in[1];
    const float* ew    = (const float*)d_in[2];
    const float* Wn    = (const float*)d_in[3];
    const float* bn    = (const float*)d_in[4];
    const float* We    = (const float*)d_in[5];
    const float* be    = (const float*)d_in[6];
    const int*   src   = (const int*)d_in[7];
    const int*   dst   = (const int*)d_in[8];
    float*       out   = (float*)d_out;

    (void)in_sizes; (void)n_in; (void)out_size;

    k_zero  <<<(N_NODES + 255) / 256, 256>>>();
    k_wsplit<<<64, 256>>>(Wn, We);
    k_hist  <<<(N_EDGES + 255) / 256, 256>>>(dst);
    k_scan1 <<<N_SCAN_BLOCKS, SCAN_BLK>>>();
    k_scan2 <<<1, 128>>>();
    k_scan3 <<<(N_NODES + 255) / 256, 256>>>();
    k_perm  <<<(N_EDGES + 255) / 256, 256>>>(src, dst, ew);
    k_gather<<<N_PANELS, 512>>>(nfeat, efeat);
    k_mgemm <<<(N_NODES + 127) / 128, 256>>>(bn, be, out);
}

// round 11
// speedup vs baseline: 1.1811x; 1.1811x over previous
#include <cuda_runtime.h>
#include <cuda_bf16.h>
#include <cstdint>

#define N_NODES 100000
#define N_EDGES 1600000
#define D 128
#define N_PANELS (N_NODES / 16)          // 6250, exact
#define SCAN_BLK 1024
#define N_SCAN_BLOCKS ((N_NODES + SCAN_BLK - 1) / SCAN_BLK)   // 98

// ---------------------------------------------------------------------------
// Device scratch
// ---------------------------------------------------------------------------
__device__ int    g_cnt [N_NODES];
__device__ int    g_cur [N_NODES];
__device__ int    g_off [N_NODES + 1];
__device__ int    g_bsum[128];
__device__ float4 g_edata[N_EDGES];                  // {eid, src, w, pad}
// A in mma-fragment layout: [panel][ks(16)][lane(32)] -> uint4 {a0,a1,a2,a3}
__device__ uint4  g_xhi4[(size_t)N_PANELS * 512];
__device__ uint4  g_xlo4[(size_t)N_PANELS * 512];
// W in fragment layout: [npp(8)][ks(16)][lane(32)][word(4)] (uint32 words)
__device__ uint32_t g_whi32[16384];
__device__ uint32_t g_wlo32[16384];

// ---------------------------------------------------------------------------
// helpers
// ---------------------------------------------------------------------------
__device__ __forceinline__ uint32_t bfpair(float a, float b) {
    __nv_bfloat162 t = __floats2bfloat162_rn(a, b);
    return *reinterpret_cast<uint32_t*>(&t);
}
__device__ __forceinline__ void mma_bf16(float* d, const uint32_t* a,
                                         uint32_t b0, uint32_t b1) {
    asm volatile(
        "mma.sync.aligned.m16n8k16.row.col.f32.bf16.bf16.f32 "
        "{%0,%1,%2,%3}, {%4,%5,%6,%7}, {%8,%9}, {%0,%1,%2,%3};"
        : "+f"(d[0]), "+f"(d[1]), "+f"(d[2]), "+f"(d[3])
        : "r"(a[0]), "r"(a[1]), "r"(a[2]), "r"(a[3]), "r"(b0), "r"(b1));
}

// ---------------------------------------------------------------------------
// Setup kernels
// ---------------------------------------------------------------------------
__global__ void k_zero() {
    int i = blockIdx.x * blockDim.x + threadIdx.x;
    if (i < N_NODES) { g_cnt[i] = 0; g_cur[i] = 0; }
}

__global__ __launch_bounds__(256) void k_hist(const int* __restrict__ dst) {
    int e = blockIdx.x * blockDim.x + threadIdx.x;
    if (e < N_EDGES) atomicAdd(&g_cnt[dst[e]], 1);
}

__global__ __launch_bounds__(SCAN_BLK) void k_scan1() {
    __shared__ int warp_pfx[32];
    const int tid = threadIdx.x;
    const int i   = blockIdx.x * SCAN_BLK + tid;
    const int v   = (i < N_NODES) ? g_cnt[i] : 0;

    int x = v;
#pragma unroll
    for (int o = 1; o < 32; o <<= 1) {
        int y = __shfl_up_sync(0xffffffffu, x, o);
        if ((tid & 31) >= o) x += y;
    }
    if ((tid & 31) == 31) warp_pfx[tid >> 5] = x;
    __syncthreads();
    if (tid < 32) {
        int t = warp_pfx[tid];
        int s = t;
#pragma unroll
        for (int o = 1; o < 32; o <<= 1) {
            int y = __shfl_up_sync(0xffffffffu, s, o);
            if (tid >= o) s += y;
        }
        warp_pfx[tid] = s - t;
        if (tid == 31) g_bsum[blockIdx.x] = s;
    }
    __syncthreads();
    if (i < N_NODES) g_off[i] = (x - v) + warp_pfx[tid >> 5];
}

__global__ __launch_bounds__(128) void k_scan2() {
    __shared__ int s[128];
    const int tid = threadIdx.x;
    const int v = (tid < N_SCAN_BLOCKS) ? g_bsum[tid] : 0;
    s[tid] = v;
    __syncthreads();
#pragma unroll
    for (int o = 1; o < 128; o <<= 1) {
        int y = (tid >= o) ? s[tid - o] : 0;
        __syncthreads();
        s[tid] += y;
        __syncthreads();
    }
    if (tid < N_SCAN_BLOCKS) g_bsum[tid] = s[tid] - v;
}

__global__ void k_scan3() {
    int i = blockIdx.x * blockDim.x + threadIdx.x;
    if (i < N_NODES) g_off[i] += g_bsum[i >> 10];
    if (i == 0) g_off[N_NODES] = N_EDGES;
}

__global__ __launch_bounds__(256) void k_perm(const int* __restrict__ src,
                                              const int* __restrict__ dst,
                                              const float* __restrict__ ew) {
    int e = blockIdx.x * blockDim.x + threadIdx.x;
    if (e >= N_EDGES) return;
    const int d   = dst[e];
    const int pos = g_off[d] + atomicAdd(&g_cur[d], 1);
    g_edata[pos] = make_float4(__int_as_float(e), __int_as_float(src[e]),
                               __ldg(ew + e), 0.f);
}

// W -> bf16 hi/lo directly in B-fragment layout
__global__ __launch_bounds__(256) void k_wsplit(const float* __restrict__ Wn,
                                                const float* __restrict__ We) {
    const int idx = blockIdx.x * blockDim.x + threadIdx.x;  // 0..16383
    if (idx >= 16384) return;
    const int e    = idx >> 2;
    const int word = idx & 3;
    const int npp  = e >> 9;          // /512
    const int rem  = e & 511;
    const int ks   = rem >> 5;
    const int lane = rem & 31;
    const int gid  = lane >> 2;
    const int tig  = lane & 3;
    const int col  = npp * 16 + (word >> 1) * 8 + gid;
    const int k    = ks * 16 + (word & 1) * 8 + tig * 2;

    float v0, v1;
    if (k < 128) { v0 = __ldg(Wn + col * 128 + k);       v1 = __ldg(Wn + col * 128 + k + 1); }
    else         { v0 = __ldg(We + col * 128 + k - 128); v1 = __ldg(We + col * 128 + k - 127); }

    const float h0 = __bfloat162float(__float2bfloat16(v0));
    const float h1 = __bfloat162float(__float2bfloat16(v1));
    g_whi32[idx] = bfpair(h0, h1);
    g_wlo32[idx] = bfpair(v0 - h0, v1 - h1);
}

// ---------------------------------------------------------------------------
// Gather (R7 version, unmodified): 512 threads = 16 warps = 1 panel.
// ---------------------------------------------------------------------------
__global__ __launch_bounds__(512) void k_gather(const float* __restrict__ nfeat,
                                                const float* __restrict__ efeat) {
    __shared__ uint32_t hi32[16][132];
    __shared__ uint32_t lo32[16][132];

    const int tid  = threadIdx.x;
    const int w    = tid >> 5;
    const int lane = tid & 31;
    const int pan  = blockIdx.x;
    const int n    = pan * 16 + w;            // always < N_NODES

    const int beg = __ldg(g_off + n);
    const int end = __ldg(g_off + n + 1);

    float4 accn = make_float4(0.f, 0.f, 0.f, 0.f);
    float4 acce = make_float4(0.f, 0.f, 0.f, 0.f);

    int i = beg;
    for (; i + 3 < end; i += 4) {
        const float4 p0 = __ldg(g_edata + i + 0);
        const float4 p1 = __ldg(g_edata + i + 1);
        const float4 p2 = __ldg(g_edata + i + 2);
        const float4 p3 = __ldg(g_edata + i + 3);
        const int e0 = __float_as_int(p0.x), s0 = __float_as_int(p0.y);
        const int e1 = __float_as_int(p1.x), s1 = __float_as_int(p1.y);
        const int e2 = __float_as_int(p2.x), s2 = __float_as_int(p2.y);
        const int e3 = __float_as_int(p3.x), s3 = __float_as_int(p3.y);
        const float w0 = p0.z, w1 = p1.z, w2 = p2.z, w3 = p3.z;

        const float4 f0 = __ldg(reinterpret_cast<const float4*>(efeat + (size_t)e0 * D) + lane);
        const float4 f1 = __ldg(reinterpret_cast<const float4*>(efeat + (size_t)e1 * D) + lane);
        const float4 f2 = __ldg(reinterpret_cast<const float4*>(efeat + (size_t)e2 * D) + lane);
        const float4 f3 = __ldg(reinterpret_cast<const float4*>(efeat + (size_t)e3 * D) + lane);
        const float4 m0 = __ldg(reinterpret_cast<const float4*>(nfeat + (size_t)s0 * D) + lane);
        const float4 m1 = __ldg(reinterpret_cast<const float4*>(nfeat + (size_t)s1 * D) + lane);
        const float4 m2 = __ldg(reinterpret_cast<const float4*>(nfeat + (size_t)s2 * D) + lane);
        const float4 m3 = __ldg(reinterpret_cast<const float4*>(nfeat + (size_t)s3 * D) + lane);

        acce.x += (f0.x + f1.x) + (f2.x + f3.x);
        acce.y += (f0.y + f1.y) + (f2.y + f3.y);
        acce.z += (f0.z + f1.z) + (f2.z + f3.z);
        acce.w += (f0.w + f1.w) + (f2.w + f3.w);
        accn.x += (w0 * m0.x + w1 * m1.x) + (w2 * m2.x + w3 * m3.x);
        accn.y += (w0 * m0.y + w1 * m1.y) + (w2 * m2.y + w3 * m3.y);
        accn.z += (w0 * m0.z + w1 * m1.z) + (w2 * m2.z + w3 * m3.z);
        accn.w += (w0 * m0.w + w1 * m1.w) + (w2 * m2.w + w3 * m3.w);
    }
    for (; i < end; i++) {
        const float4 p = __ldg(g_edata + i);
        const int e = __float_as_int(p.x), s = __float_as_int(p.y);
        const float wt = p.z;
        const float4 f  = __ldg(reinterpret_cast<const float4*>(efeat + (size_t)e * D) + lane);
        const float4 mm = __ldg(reinterpret_cast<const float4*>(nfeat + (size_t)s * D) + lane);
        acce.x += f.x; acce.y += f.y; acce.z += f.z; acce.w += f.w;
        accn.x += wt * mm.x; accn.y += wt * mm.y; accn.z += wt * mm.z; accn.w += wt * mm.w;
    }

    const float deg = (float)(end - beg);
    const float rd1 = 1.f / (deg + 1.f);
    const float rd2 = 1.f / fmaxf(deg, 1.f);

    const float4 self = __ldg(reinterpret_cast<const float4*>(nfeat + (size_t)n * D) + lane);
    float x1[4], x2[4];
    x1[0] = (accn.x + 2.f * self.x) * rd1;
    x1[1] = (accn.y + 2.f * self.y) * rd1;
    x1[2] = (accn.z + 2.f * self.z) * rd1;
    x1[3] = (accn.w + 2.f * self.w) * rd1;
    x2[0] = acce.x * rd2; x2[1] = acce.y * rd2;
    x2[2] = acce.z * rd2; x2[3] = acce.w * rd2;

    float h1[4], h2[4];
#pragma unroll
    for (int j = 0; j < 4; j++) {
        h1[j] = __bfloat162float(__float2bfloat16(x1[j]));
        h2[j] = __bfloat162float(__float2bfloat16(x2[j]));
    }
    {
        uint2 a, b;
        a.x = bfpair(h1[0], h1[1]);             a.y = bfpair(h1[2], h1[3]);
        b.x = bfpair(x1[0]-h1[0], x1[1]-h1[1]); b.y = bfpair(x1[2]-h1[2], x1[3]-h1[3]);
        *reinterpret_cast<uint2*>(&hi32[w][2 * lane]) = a;
        *reinterpret_cast<uint2*>(&lo32[w][2 * lane]) = b;
    }
    {
        uint2 a, b;
        a.x = bfpair(h2[0], h2[1]);             a.y = bfpair(h2[2], h2[3]);
        b.x = bfpair(x2[0]-h2[0], x2[1]-h2[1]); b.y = bfpair(x2[2]-h2[2], x2[3]-h2[3]);
        *reinterpret_cast<uint2*>(&hi32[w][64 + 2 * lane]) = a;
        *reinterpret_cast<uint2*>(&lo32[w][64 + 2 * lane]) = b;
    }
    __syncthreads();

    {
        const int ks  = w;
        const int gid = lane >> 2;
        const int tig = lane & 3;
        uint4 vh, vl;
        vh.x = hi32[gid    ][ks * 8 + tig];
        vh.y = hi32[gid + 8][ks * 8 + tig];
        vh.z = hi32[gid    ][ks * 8 + 4 + tig];
        vh.w = hi32[gid + 8][ks * 8 + 4 + tig];
        vl.x = lo32[gid    ][ks * 8 + tig];
        vl.y = lo32[gid + 8][ks * 8 + tig];
        vl.z = lo32[gid    ][ks * 8 + 4 + tig];
        vl.w = lo32[gid + 8][ks * 8 + 4 + tig];
        const size_t eidx = ((size_t)pan * 16 + ks) * 32 + lane;
        g_xhi4[eidx] = vh;
        g_xlo4[eidx] = vl;
    }
}

// ---------------------------------------------------------------------------
// HMMA GEMM, passes fused into the ks loop + A register double-buffer.
// 256 threads = 8 warps; block 128 rows x 128 cols; warp tile 32x64.
// Per ks: load Ahi/Alo (4 LDG) + Bhi/Blo (8 LDG), issue 48 mma.
// ---------------------------------------------------------------------------
__global__ __launch_bounds__(256) void k_mgemm(const float* __restrict__ bn,
                                               const float* __restrict__ be,
                                               float* __restrict__ out) {
    const int bx   = blockIdx.x;
    const int tid  = threadIdx.x;
    const int w    = tid >> 5;
    const int lane = tid & 31;
    const int gid  = lane >> 2;
    const int tig  = lane & 3;
    const int warp_m = (w & 3) * 32;
    const int warp_n = (w >> 2) * 64;
    const int n0   = bx * 128;
    const int nppb = (w >> 2) * 4;

    float acc[2][8][4];
#pragma unroll
    for (int mt = 0; mt < 2; mt++)
#pragma unroll
        for (int nt = 0; nt < 8; nt++)
#pragma unroll
            for (int j = 0; j < 4; j++) acc[mt][nt][j] = 0.f;

    int  pan[2];
    bool pv[2];
#pragma unroll
    for (int mt = 0; mt < 2; mt++) {
        pan[mt] = bx * 8 + (w & 3) * 2 + mt;
        pv[mt]  = pan[mt] < N_PANELS;
    }

    const uint4* Bhi4 = reinterpret_cast<const uint4*>(g_whi32);
    const uint4* Blo4 = reinterpret_cast<const uint4*>(g_wlo32);

    uint4 ah[2][2], al[2][2];   // [buf][mt]

    auto loadA = [&](int ks, uint4* ah_, uint4* al_) {
#pragma unroll
        for (int mt = 0; mt < 2; mt++) {
            ah_[mt] = make_uint4(0, 0, 0, 0);
            al_[mt] = make_uint4(0, 0, 0, 0);
            if (pv[mt]) {
                const size_t idx = (size_t)(pan[mt] * 16 + ks) * 32 + lane;
                ah_[mt] = __ldg(g_xhi4 + idx);
                al_[mt] = __ldg(g_xlo4 + idx);
            }
        }
    };

    loadA(0, ah[0], al[0]);

#pragma unroll 2
    for (int ks = 0; ks < 16; ks++) {
        const int buf = ks & 1;
        if (ks < 15) loadA(ks + 1, ah[buf ^ 1], al[buf ^ 1]);   // overlap with mma

#pragma unroll
        for (int npq = 0; npq < 4; npq++) {
            const size_t bidx = ((size_t)(nppb + npq) * 16 + ks) * 32 + lane;
            const uint4 bh = __ldg(Bhi4 + bidx);
            const uint4 bl = __ldg(Blo4 + bidx);
#pragma unroll
            for (int mt = 0; mt < 2; mt++) {
                const uint32_t* aH = reinterpret_cast<const uint32_t*>(&ah[buf][mt]);
                const uint32_t* aL = reinterpret_cast<const uint32_t*>(&al[buf][mt]);
                mma_bf16(acc[mt][npq * 2 + 0], aH, bh.x, bh.y);
                mma_bf16(acc[mt][npq * 2 + 1], aH, bh.z, bh.w);
                mma_bf16(acc[mt][npq * 2 + 0], aH, bl.x, bl.y);
                mma_bf16(acc[mt][npq * 2 + 1], aH, bl.z, bl.w);
                mma_bf16(acc[mt][npq * 2 + 0], aL, bh.x, bh.y);
                mma_bf16(acc[mt][npq * 2 + 1], aL, bh.z, bh.w);
            }
        }
    }

    // ---- epilogue ----
#pragma unroll
    for (int mt = 0; mt < 2; mt++) {
        const int rA = n0 + warp_m + mt * 16 + gid;
        const int rB = rA + 8;
        const bool vA = rA < N_NODES;
        const bool vB = rB < N_NODES;
        float fA = 0.f, fB = 0.f;
        if (vA) fA = (__ldg(g_off + rA + 1) - __ldg(g_off + rA) > 0) ? 1.f : 0.f;
        if (vB) fB = (__ldg(g_off + rB + 1) - __ldg(g_off + rB) > 0) ? 1.f : 0.f;

#pragma unroll
        for (int nt = 0; nt < 8; nt++) {
            const int col = warp_n + nt * 8 + tig * 2;
            const float2 bnv = __ldg(reinterpret_cast<const float2*>(bn + col));
            const float2 bev = __ldg(reinterpret_cast<const float2*>(be + col));
            if (vA) {
                float2 o;
                o.x = acc[mt][nt][0] + bnv.x + fA * bev.x;
                o.y = acc[mt][nt][1] + bnv.y + fA * bev.y;
                *reinterpret_cast<float2*>(out + (size_t)rA * 128 + col) = o;
            }
            if (vB) {
                float2 o;
                o.x = acc[mt][nt][2] + bnv.x + fB * bev.x;
                o.y = acc[mt][nt][3] + bnv.y + fB * bev.y;
                *reinterpret_cast<float2*>(out + (size_t)rB * 128 + col) = o;
            }
        }
    }
}

// ---------------------------------------------------------------------------
extern "C" void kernel_launch(void* const* d_in, const int* in_sizes, int n_in,
                              void* d_out, int out_size) {
    const float* nfeat = (const float*)d_in[0];
    const float* efeat = (const float*)d_in[1];
    const float* ew    = (const float*)d_in[2];
    const float* Wn    = (const float*)d_in[3];
    const float* bn    = (const float*)d_in[4];
    const float* We    = (const float*)d_in[5];
    const float* be    = (const float*)d_in[6];
    const int*   src   = (const int*)d_in[7];
    const int*   dst   = (const int*)d_in[8];
    float*       out   = (float*)d_out;

    (void)in_sizes; (void)n_in; (void)out_size;

    k_zero  <<<(N_NODES + 255) / 256, 256>>>();
    k_wsplit<<<64, 256>>>(Wn, We);
    k_hist  <<<(N_EDGES + 255) / 256, 256>>>(dst);
    k_scan1 <<<N_SCAN_BLOCKS, SCAN_BLK>>>();
    k_scan2 <<<1, 128>>>();
    k_scan3 <<<(N_NODES + 255) / 256, 256>>>();
    k_perm  <<<(N_EDGES + 255) / 256, 256>>>(src, dst, ew);
    k_gather<<<N_PANELS, 512>>>(nfeat, efeat);
    k_mgemm <<<(N_NODES + 127) / 128, 256>>>(bn, be, out);
}

// round 12
// speedup vs baseline: 1.4393x; 1.2186x over previous
#include <cuda_runtime.h>
#include <cuda_fp16.h>
#include <cstdint>

#define N_NODES 100000
#define N_EDGES 1600000
#define D 128
#define N_PANELS (N_NODES / 16)          // 6250, exact
#define SCAN_BLK 1024
#define N_SCAN_BLOCKS ((N_NODES + SCAN_BLK - 1) / SCAN_BLK)   // 98

// ---------------------------------------------------------------------------
// Device scratch
// ---------------------------------------------------------------------------
__device__ int    g_cnt [N_NODES];
__device__ int    g_cur [N_NODES];
__device__ int    g_off [N_NODES + 1];
__device__ int    g_bsum[128];
__device__ float4 g_edata[N_EDGES];                  // {eid, src, w, pad}
// A in mma-fragment layout (fp16): [panel][ks(16)][lane(32)] -> uint4
__device__ uint4  g_xh4[(size_t)N_PANELS * 512];
// W in fragment layout (fp16): [npp(8)][ks(16)][lane(32)][word(4)]
__device__ uint32_t g_wh32[16384];

// ---------------------------------------------------------------------------
// helpers
// ---------------------------------------------------------------------------
__device__ __forceinline__ uint32_t hpair(float a, float b) {
    __half2 t = __floats2half2_rn(a, b);
    return *reinterpret_cast<uint32_t*>(&t);
}
__device__ __forceinline__ void mma_f16(float* d, const uint32_t* a,
                                        uint32_t b0, uint32_t b1) {
    asm volatile(
        "mma.sync.aligned.m16n8k16.row.col.f32.f16.f16.f32 "
        "{%0,%1,%2,%3}, {%4,%5,%6,%7}, {%8,%9}, {%0,%1,%2,%3};"
        : "+f"(d[0]), "+f"(d[1]), "+f"(d[2]), "+f"(d[3])
        : "r"(a[0]), "r"(a[1]), "r"(a[2]), "r"(a[3]), "r"(b0), "r"(b1));
}

// ---------------------------------------------------------------------------
// Setup kernels
// ---------------------------------------------------------------------------
__global__ void k_zero() {
    int i = blockIdx.x * blockDim.x + threadIdx.x;
    if (i < N_NODES) { g_cnt[i] = 0; g_cur[i] = 0; }
}

__global__ __launch_bounds__(256) void k_hist(const int* __restrict__ dst) {
    int e = blockIdx.x * blockDim.x + threadIdx.x;
    if (e < N_EDGES) atomicAdd(&g_cnt[dst[e]], 1);
}

__global__ __launch_bounds__(SCAN_BLK) void k_scan1() {
    __shared__ int warp_pfx[32];
    const int tid = threadIdx.x;
    const int i   = blockIdx.x * SCAN_BLK + tid;
    const int v   = (i < N_NODES) ? g_cnt[i] : 0;

    int x = v;
#pragma unroll
    for (int o = 1; o < 32; o <<= 1) {
        int y = __shfl_up_sync(0xffffffffu, x, o);
        if ((tid & 31) >= o) x += y;
    }
    if ((tid & 31) == 31) warp_pfx[tid >> 5] = x;
    __syncthreads();
    if (tid < 32) {
        int t = warp_pfx[tid];
        int s = t;
#pragma unroll
        for (int o = 1; o < 32; o <<= 1) {
            int y = __shfl_up_sync(0xffffffffu, s, o);
            if (tid >= o) s += y;
        }
        warp_pfx[tid] = s - t;
        if (tid == 31) g_bsum[blockIdx.x] = s;
    }
    __syncthreads();
    if (i < N_NODES) g_off[i] = (x - v) + warp_pfx[tid >> 5];
}

__global__ __launch_bounds__(128) void k_scan2() {
    __shared__ int s[128];
    const int tid = threadIdx.x;
    const int v = (tid < N_SCAN_BLOCKS) ? g_bsum[tid] : 0;
    s[tid] = v;
    __syncthreads();
#pragma unroll
    for (int o = 1; o < 128; o <<= 1) {
        int y = (tid >= o) ? s[tid - o] : 0;
        __syncthreads();
        s[tid] += y;
        __syncthreads();
    }
    if (tid < N_SCAN_BLOCKS) g_bsum[tid] = s[tid] - v;
}

__global__ void k_scan3() {
    int i = blockIdx.x * blockDim.x + threadIdx.x;
    if (i < N_NODES) g_off[i] += g_bsum[i >> 10];
    if (i == 0) g_off[N_NODES] = N_EDGES;
}

__global__ __launch_bounds__(256) void k_perm(const int* __restrict__ src,
                                              const int* __restrict__ dst,
                                              const float* __restrict__ ew) {
    int e = blockIdx.x * blockDim.x + threadIdx.x;
    if (e >= N_EDGES) return;
    const int d   = dst[e];
    const int pos = g_off[d] + atomicAdd(&g_cur[d], 1);
    g_edata[pos] = make_float4(__int_as_float(e), __int_as_float(src[e]),
                               __ldg(ew + e), 0.f);
}

// W -> fp16 directly in B-fragment layout
__global__ __launch_bounds__(256) void k_wsplit(const float* __restrict__ Wn,
                                                const float* __restrict__ We) {
    const int idx = blockIdx.x * blockDim.x + threadIdx.x;  // 0..16383
    if (idx >= 16384) return;
    const int e    = idx >> 2;
    const int word = idx & 3;
    const int npp  = e >> 9;          // /512
    const int rem  = e & 511;
    const int ks   = rem >> 5;
    const int lane = rem & 31;
    const int gid  = lane >> 2;
    const int tig  = lane & 3;
    const int col  = npp * 16 + (word >> 1) * 8 + gid;
    const int k    = ks * 16 + (word & 1) * 8 + tig * 2;

    float v0, v1;
    if (k < 128) { v0 = __ldg(Wn + col * 128 + k);       v1 = __ldg(Wn + col * 128 + k + 1); }
    else         { v0 = __ldg(We + col * 128 + k - 128); v1 = __ldg(We + col * 128 + k - 127); }

    g_wh32[idx] = hpair(v0, v1);
}

// ---------------------------------------------------------------------------
// Gather: 512 threads = 16 warps = 1 panel (16 nodes). Warp w gathers node
// blockIdx.x*16+w; smem transpose into fp16 A-fragment layout.
// ---------------------------------------------------------------------------
__global__ __launch_bounds__(512) void k_gather(const float* __restrict__ nfeat,
                                                const float* __restrict__ efeat) {
    __shared__ uint32_t h32[16][132];

    const int tid  = threadIdx.x;
    const int w    = tid >> 5;
    const int lane = tid & 31;
    const int pan  = blockIdx.x;
    const int n    = pan * 16 + w;            // always < N_NODES

    const int beg = __ldg(g_off + n);
    const int end = __ldg(g_off + n + 1);

    float4 accn = make_float4(0.f, 0.f, 0.f, 0.f);
    float4 acce = make_float4(0.f, 0.f, 0.f, 0.f);

    int i = beg;
    for (; i + 3 < end; i += 4) {
        const float4 p0 = __ldg(g_edata + i + 0);
        const float4 p1 = __ldg(g_edata + i + 1);
        const float4 p2 = __ldg(g_edata + i + 2);
        const float4 p3 = __ldg(g_edata + i + 3);
        const int e0 = __float_as_int(p0.x), s0 = __float_as_int(p0.y);
        const int e1 = __float_as_int(p1.x), s1 = __float_as_int(p1.y);
        const int e2 = __float_as_int(p2.x), s2 = __float_as_int(p2.y);
        const int e3 = __float_as_int(p3.x), s3 = __float_as_int(p3.y);
        const float w0 = p0.z, w1 = p1.z, w2 = p2.z, w3 = p3.z;

        const float4 f0 = __ldg(reinterpret_cast<const float4*>(efeat + (size_t)e0 * D) + lane);
        const float4 f1 = __ldg(reinterpret_cast<const float4*>(efeat + (size_t)e1 * D) + lane);
        const float4 f2 = __ldg(reinterpret_cast<const float4*>(efeat + (size_t)e2 * D) + lane);
        const float4 f3 = __ldg(reinterpret_cast<const float4*>(efeat + (size_t)e3 * D) + lane);
        const float4 m0 = __ldg(reinterpret_cast<const float4*>(nfeat + (size_t)s0 * D) + lane);
        const float4 m1 = __ldg(reinterpret_cast<const float4*>(nfeat + (size_t)s1 * D) + lane);
        const float4 m2 = __ldg(reinterpret_cast<const float4*>(nfeat + (size_t)s2 * D) + lane);
        const float4 m3 = __ldg(reinterpret_cast<const float4*>(nfeat + (size_t)s3 * D) + lane);

        acce.x += (f0.x + f1.x) + (f2.x + f3.x);
        acce.y += (f0.y + f1.y) + (f2.y + f3.y);
        acce.z += (f0.z + f1.z) + (f2.z + f3.z);
        acce.w += (f0.w + f1.w) + (f2.w + f3.w);
        accn.x += (w0 * m0.x + w1 * m1.x) + (w2 * m2.x + w3 * m3.x);
        accn.y += (w0 * m0.y + w1 * m1.y) + (w2 * m2.y + w3 * m3.y);
        accn.z += (w0 * m0.z + w1 * m1.z) + (w2 * m2.z + w3 * m3.z);
        accn.w += (w0 * m0.w + w1 * m1.w) + (w2 * m2.w + w3 * m3.w);
    }
    for (; i < end; i++) {
        const float4 p = __ldg(g_edata + i);
        const int e = __float_as_int(p.x), s = __float_as_int(p.y);
        const float wt = p.z;
        const float4 f  = __ldg(reinterpret_cast<const float4*>(efeat + (size_t)e * D) + lane);
        const float4 mm = __ldg(reinterpret_cast<const float4*>(nfeat + (size_t)s * D) + lane);
        acce.x += f.x; acce.y += f.y; acce.z += f.z; acce.w += f.w;
        accn.x += wt * mm.x; accn.y += wt * mm.y; accn.z += wt * mm.z; accn.w += wt * mm.w;
    }

    const float deg = (float)(end - beg);
    const float rd1 = 1.f / (deg + 1.f);
    const float rd2 = 1.f / fmaxf(deg, 1.f);

    const float4 self = __ldg(reinterpret_cast<const float4*>(nfeat + (size_t)n * D) + lane);
    float x1[4], x2[4];
    x1[0] = (accn.x + 2.f * self.x) * rd1;
    x1[1] = (accn.y + 2.f * self.y) * rd1;
    x1[2] = (accn.z + 2.f * self.z) * rd1;
    x1[3] = (accn.w + 2.f * self.w) * rd1;
    x2[0] = acce.x * rd2; x2[1] = acce.y * rd2;
    x2[2] = acce.z * rd2; x2[3] = acce.w * rd2;

    {
        uint2 a;
        a.x = hpair(x1[0], x1[1]);  a.y = hpair(x1[2], x1[3]);
        *reinterpret_cast<uint2*>(&h32[w][2 * lane]) = a;
        uint2 b;
        b.x = hpair(x2[0], x2[1]);  b.y = hpair(x2[2], x2[3]);
        *reinterpret_cast<uint2*>(&h32[w][64 + 2 * lane]) = b;
    }
    __syncthreads();

    {
        const int ks  = w;
        const int gid = lane >> 2;
        const int tig = lane & 3;
        uint4 vh;
        vh.x = h32[gid    ][ks * 8 + tig];
        vh.y = h32[gid + 8][ks * 8 + tig];
        vh.z = h32[gid    ][ks * 8 + 4 + tig];
        vh.w = h32[gid + 8][ks * 8 + 4 + tig];
        const size_t eidx = ((size_t)pan * 16 + ks) * 32 + lane;
        g_xh4[eidx] = vh;
    }
}

// ---------------------------------------------------------------------------
// fp16 HMMA GEMM, single pass. 256 threads = 8 warps.
// Block: 128 rows (8 panels) x 128 cols. Warp tile 32(M) x 64(N).
// 256 mma/warp; A register double-buffered.
// ---------------------------------------------------------------------------
__global__ __launch_bounds__(256) void k_mgemm(const float* __restrict__ bn,
                                               const float* __restrict__ be,
                                               float* __restrict__ out) {
    const int bx   = blockIdx.x;
    const int tid  = threadIdx.x;
    const int w    = tid >> 5;
    const int lane = tid & 31;
    const int gid  = lane >> 2;
    const int tig  = lane & 3;
    const int warp_m = (w & 3) * 32;
    const int warp_n = (w >> 2) * 64;
    const int n0   = bx * 128;
    const int nppb = (w >> 2) * 4;

    float acc[2][8][4];
#pragma unroll
    for (int mt = 0; mt < 2; mt++)
#pragma unroll
        for (int nt = 0; nt < 8; nt++)
#pragma unroll
            for (int j = 0; j < 4; j++) acc[mt][nt][j] = 0.f;

    int  pan[2];
    bool pv[2];
#pragma unroll
    for (int mt = 0; mt < 2; mt++) {
        pan[mt] = bx * 8 + (w & 3) * 2 + mt;
        pv[mt]  = pan[mt] < N_PANELS;
    }

    const uint4* B4 = reinterpret_cast<const uint4*>(g_wh32);

    uint4 abuf[2][2];   // [buf][mt]
    auto loadA = [&](int ks, uint4* a_) {
#pragma unroll
        for (int mt = 0; mt < 2; mt++) {
            a_[mt] = make_uint4(0, 0, 0, 0);
            if (pv[mt])
                a_[mt] = __ldg(g_xh4 + ((size_t)(pan[mt] * 16 + ks) * 32 + lane));
        }
    };

    loadA(0, abuf[0]);

#pragma unroll 4
    for (int ks = 0; ks < 16; ks++) {
        const int buf = ks & 1;
        if (ks < 15) loadA(ks + 1, abuf[buf ^ 1]);   // overlap with mma

#pragma unroll
        for (int npq = 0; npq < 4; npq++) {
            const uint4 b4 = __ldg(B4 + (((size_t)(nppb + npq) * 16 + ks) * 32 + lane));
#pragma unroll
            for (int mt = 0; mt < 2; mt++) {
                const uint32_t* aF = reinterpret_cast<const uint32_t*>(&abuf[buf][mt]);
                mma_f16(acc[mt][npq * 2 + 0], aF, b4.x, b4.y);
                mma_f16(acc[mt][npq * 2 + 1], aF, b4.z, b4.w);
            }
        }
    }

    // ---- epilogue ----
#pragma unroll
    for (int mt = 0; mt < 2; mt++) {
        const int rA = n0 + warp_m + mt * 16 + gid;
        const int rB = rA + 8;
        const bool vA = rA < N_NODES;
        const bool vB = rB < N_NODES;
        float fA = 0.f, fB = 0.f;
        if (vA) fA = (__ldg(g_off + rA + 1) - __ldg(g_off + rA) > 0) ? 1.f : 0.f;
        if (vB) fB = (__ldg(g_off + rB + 1) - __ldg(g_off + rB) > 0) ? 1.f : 0.f;

#pragma unroll
        for (int nt = 0; nt < 8; nt++) {
            const int col = warp_n + nt * 8 + tig * 2;
            const float2 bnv = __ldg(reinterpret_cast<const float2*>(bn + col));
            const float2 bev = __ldg(reinterpret_cast<const float2*>(be + col));
            if (vA) {
                float2 o;
                o.x = acc[mt][nt][0] + bnv.x + fA * bev.x;
                o.y = acc[mt][nt][1] + bnv.y + fA * bev.y;
                *reinterpret_cast<float2*>(out + (size_t)rA * 128 + col) = o;
            }
            if (vB) {
                float2 o;
                o.x = acc[mt][nt][2] + bnv.x + fB * bev.x;
                o.y = acc[mt][nt][3] + bnv.y + fB * bev.y;
                *reinterpret_cast<float2*>(out + (size_t)rB * 128 + col) = o;
            }
        }
    }
}

// ---------------------------------------------------------------------------
extern "C" void kernel_launch(void* const* d_in, const int* in_sizes, int n_in,
                              void* d_out, int out_size) {
    const float* nfeat = (const float*)d_in[0];
    const float* efeat = (const float*)d_in[1];
    const float* ew    = (const float*)d_in[2];
    const float* Wn    = (const float*)d_in[3];
    const float* bn    = (const float*)d_in[4];
    const float* We    = (const float*)d_in[5];
    const float* be    = (const float*)d_in[6];
    const int*   src   = (const int*)d_in[7];
    const int*   dst   = (const int*)d_in[8];
    float*       out   = (float*)d_out;

    (void)in_sizes; (void)n_in; (void)out_size;

    k_zero  <<<(N_NODES + 255) / 256, 256>>>();
    k_wsplit<<<64, 256>>>(Wn, We);
    k_hist  <<<(N_EDGES + 255) / 256, 256>>>(dst);
    k_scan1 <<<N_SCAN_BLOCKS, SCAN_BLK>>>();
    k_scan2 <<<1, 128>>>();
    k_scan3 <<<(N_NODES + 255) / 256, 256>>>();
    k_perm  <<<(N_EDGES + 255) / 256, 256>>>(src, dst, ew);
    k_gather<<<N_PANELS, 512>>>(nfeat, efeat);
    k_mgemm <<<(N_NODES + 127) / 128, 256>>>(bn, be, out);
}

// round 13
// speedup vs baseline: 1.6147x; 1.1219x over previous
#include <cuda_runtime.h>
#include <cuda_fp16.h>
#include <cstdint>

#define N_NODES 100000
#define N_EDGES 1600000
#define D 128
#define N_PANELS (N_NODES / 16)          // 6250, exact
#define SCAN_BLK 1024
#define N_SCAN_BLOCKS ((N_NODES + SCAN_BLK - 1) / SCAN_BLK)   // 98

// ---------------------------------------------------------------------------
// Device scratch
// ---------------------------------------------------------------------------
__device__ int    g_cnt [N_NODES];
__device__ int    g_cur [N_NODES];
__device__ int    g_off [N_NODES + 1];
__device__ int    g_bsum[128];
__device__ float4 g_edata[N_EDGES];                  // {eid, src, w, pad}
__device__ __half g_nh [(size_t)N_NODES * D];        // nfeat in fp16 (25.6 MB)
// A in mma-fragment layout (fp16): [panel][ks(16)][lane(32)] -> uint4
__device__ uint4  g_xh4[(size_t)N_PANELS * 512];
// W in fragment layout (fp16): [npp(8)][ks(16)][lane(32)][word(4)]
__device__ uint32_t g_wh32[16384];

// ---------------------------------------------------------------------------
// helpers
// ---------------------------------------------------------------------------
__device__ __forceinline__ uint32_t hpair(float a, float b) {
    __half2 t = __floats2half2_rn(a, b);
    return *reinterpret_cast<uint32_t*>(&t);
}
__device__ __forceinline__ float4 h4_to_f4(uint2 h) {
    float2 a = __half22float2(*reinterpret_cast<__half2*>(&h.x));
    float2 b = __half22float2(*reinterpret_cast<__half2*>(&h.y));
    return make_float4(a.x, a.y, b.x, b.y);
}
__device__ __forceinline__ void mma_f16(float* d, const uint32_t* a,
                                        uint32_t b0, uint32_t b1) {
    asm volatile(
        "mma.sync.aligned.m16n8k16.row.col.f32.f16.f16.f32 "
        "{%0,%1,%2,%3}, {%4,%5,%6,%7}, {%8,%9}, {%0,%1,%2,%3};"
        : "+f"(d[0]), "+f"(d[1]), "+f"(d[2]), "+f"(d[3])
        : "r"(a[0]), "r"(a[1]), "r"(a[2]), "r"(a[3]), "r"(b0), "r"(b1));
}

// ---------------------------------------------------------------------------
// Setup kernels
// ---------------------------------------------------------------------------
// zero counters + convert nfeat -> fp16 (one pass)
__global__ __launch_bounds__(256) void k_nsplit(const float* __restrict__ nf) {
    const int i = blockIdx.x * blockDim.x + threadIdx.x;   // 0 .. 3.2M-1
    if (i < N_NODES) { g_cnt[i] = 0; g_cur[i] = 0; }
    if (i < N_NODES * (D / 4)) {
        const float4 v = __ldg(reinterpret_cast<const float4*>(nf) + i);
        uint2 h;
        h.x = hpair(v.x, v.y);
        h.y = hpair(v.z, v.w);
        reinterpret_cast<uint2*>(g_nh)[i] = h;
    }
}

__global__ __launch_bounds__(256) void k_hist(const int* __restrict__ dst) {
    int e = blockIdx.x * blockDim.x + threadIdx.x;
    if (e < N_EDGES) atomicAdd(&g_cnt[dst[e]], 1);
}

__global__ __launch_bounds__(SCAN_BLK) void k_scan1() {
    __shared__ int warp_pfx[32];
    const int tid = threadIdx.x;
    const int i   = blockIdx.x * SCAN_BLK + tid;
    const int v   = (i < N_NODES) ? g_cnt[i] : 0;

    int x = v;
#pragma unroll
    for (int o = 1; o < 32; o <<= 1) {
        int y = __shfl_up_sync(0xffffffffu, x, o);
        if ((tid & 31) >= o) x += y;
    }
    if ((tid & 31) == 31) warp_pfx[tid >> 5] = x;
    __syncthreads();
    if (tid < 32) {
        int t = warp_pfx[tid];
        int s = t;
#pragma unroll
        for (int o = 1; o < 32; o <<= 1) {
            int y = __shfl_up_sync(0xffffffffu, s, o);
            if (tid >= o) s += y;
        }
        warp_pfx[tid] = s - t;
        if (tid == 31) g_bsum[blockIdx.x] = s;
    }
    __syncthreads();
    if (i < N_NODES) g_off[i] = (x - v) + warp_pfx[tid >> 5];
}

__global__ __launch_bounds__(128) void k_scan2() {
    __shared__ int s[128];
    const int tid = threadIdx.x;
    const int v = (tid < N_SCAN_BLOCKS) ? g_bsum[tid] : 0;
    s[tid] = v;
    __syncthreads();
#pragma unroll
    for (int o = 1; o < 128; o <<= 1) {
        int y = (tid >= o) ? s[tid - o] : 0;
        __syncthreads();
        s[tid] += y;
        __syncthreads();
    }
    if (tid < N_SCAN_BLOCKS) g_bsum[tid] = s[tid] - v;
}

__global__ void k_scan3() {
    int i = blockIdx.x * blockDim.x + threadIdx.x;
    if (i < N_NODES) g_off[i] += g_bsum[i >> 10];
    if (i == 0) g_off[N_NODES] = N_EDGES;
}

__global__ __launch_bounds__(256) void k_perm(const int* __restrict__ src,
                                              const int* __restrict__ dst,
                                              const float* __restrict__ ew) {
    int e = blockIdx.x * blockDim.x + threadIdx.x;
    if (e >= N_EDGES) return;
    const int d   = dst[e];
    const int pos = g_off[d] + atomicAdd(&g_cur[d], 1);
    g_edata[pos] = make_float4(__int_as_float(e), __int_as_float(src[e]),
                               __ldg(ew + e), 0.f);
}

// W -> fp16 directly in B-fragment layout
__global__ __launch_bounds__(256) void k_wsplit(const float* __restrict__ Wn,
                                                const float* __restrict__ We) {
    const int idx = blockIdx.x * blockDim.x + threadIdx.x;  // 0..16383
    if (idx >= 16384) return;
    const int e    = idx >> 2;
    const int word = idx & 3;
    const int npp  = e >> 9;          // /512
    const int rem  = e & 511;
    const int ks   = rem >> 5;
    const int lane = rem & 31;
    const int gid  = lane >> 2;
    const int tig  = lane & 3;
    const int col  = npp * 16 + (word >> 1) * 8 + gid;
    const int k    = ks * 16 + (word & 1) * 8 + tig * 2;

    float v0, v1;
    if (k < 128) { v0 = __ldg(Wn + col * 128 + k);       v1 = __ldg(Wn + col * 128 + k + 1); }
    else         { v0 = __ldg(We + col * 128 + k - 128); v1 = __ldg(We + col * 128 + k - 127); }

    g_wh32[idx] = hpair(v0, v1);
}

// ---------------------------------------------------------------------------
// Gather: 512 threads = 16 warps = 1 panel (16 nodes). Warp w gathers node
// blockIdx.x*16+w. nfeat read from the fp16 copy (L2-resident, half traffic);
// efeat streamed fp32. smem transpose into fp16 A-fragment layout.
// ---------------------------------------------------------------------------
__global__ __launch_bounds__(512) void k_gather(const float* __restrict__ efeat) {
    __shared__ uint32_t h32[16][132];

    const int tid  = threadIdx.x;
    const int w    = tid >> 5;
    const int lane = tid & 31;
    const int pan  = blockIdx.x;
    const int n    = pan * 16 + w;            // always < N_NODES

    const int beg = __ldg(g_off + n);
    const int end = __ldg(g_off + n + 1);

    float4 accn = make_float4(0.f, 0.f, 0.f, 0.f);
    float4 acce = make_float4(0.f, 0.f, 0.f, 0.f);

    const uint2* nh2 = reinterpret_cast<const uint2*>(g_nh);

    int i = beg;
    for (; i + 3 < end; i += 4) {
        const float4 p0 = __ldg(g_edata + i + 0);
        const float4 p1 = __ldg(g_edata + i + 1);
        const float4 p2 = __ldg(g_edata + i + 2);
        const float4 p3 = __ldg(g_edata + i + 3);
        const int e0 = __float_as_int(p0.x), s0 = __float_as_int(p0.y);
        const int e1 = __float_as_int(p1.x), s1 = __float_as_int(p1.y);
        const int e2 = __float_as_int(p2.x), s2 = __float_as_int(p2.y);
        const int e3 = __float_as_int(p3.x), s3 = __float_as_int(p3.y);
        const float w0 = p0.z, w1 = p1.z, w2 = p2.z, w3 = p3.z;

        const float4 f0 = __ldg(reinterpret_cast<const float4*>(efeat + (size_t)e0 * D) + lane);
        const float4 f1 = __ldg(reinterpret_cast<const float4*>(efeat + (size_t)e1 * D) + lane);
        const float4 f2 = __ldg(reinterpret_cast<const float4*>(efeat + (size_t)e2 * D) + lane);
        const float4 f3 = __ldg(reinterpret_cast<const float4*>(efeat + (size_t)e3 * D) + lane);
        const uint2  h0 = __ldg(nh2 + (size_t)s0 * 32 + lane);
        const uint2  h1 = __ldg(nh2 + (size_t)s1 * 32 + lane);
        const uint2  h2 = __ldg(nh2 + (size_t)s2 * 32 + lane);
        const uint2  h3 = __ldg(nh2 + (size_t)s3 * 32 + lane);

        const float4 m0 = h4_to_f4(h0);
        const float4 m1 = h4_to_f4(h1);
        const float4 m2 = h4_to_f4(h2);
        const float4 m3 = h4_to_f4(h3);

        acce.x += (f0.x + f1.x) + (f2.x + f3.x);
        acce.y += (f0.y + f1.y) + (f2.y + f3.y);
        acce.z += (f0.z + f1.z) + (f2.z + f3.z);
        acce.w += (f0.w + f1.w) + (f2.w + f3.w);
        accn.x += (w0 * m0.x + w1 * m1.x) + (w2 * m2.x + w3 * m3.x);
        accn.y += (w0 * m0.y + w1 * m1.y) + (w2 * m2.y + w3 * m3.y);
        accn.z += (w0 * m0.z + w1 * m1.z) + (w2 * m2.z + w3 * m3.z);
        accn.w += (w0 * m0.w + w1 * m1.w) + (w2 * m2.w + w3 * m3.w);
    }
    for (; i < end; i++) {
        const float4 p = __ldg(g_edata + i);
        const int e = __float_as_int(p.x), s = __float_as_int(p.y);
        const float wt = p.z;
        const float4 f  = __ldg(reinterpret_cast<const float4*>(efeat + (size_t)e * D) + lane);
        const float4 mm = h4_to_f4(__ldg(nh2 + (size_t)s * 32 + lane));
        acce.x += f.x; acce.y += f.y; acce.z += f.z; acce.w += f.w;
        accn.x += wt * mm.x; accn.y += wt * mm.y; accn.z += wt * mm.z; accn.w += wt * mm.w;
    }

    const float deg = (float)(end - beg);
    const float rd1 = 1.f / (deg + 1.f);
    const float rd2 = 1.f / fmaxf(deg, 1.f);

    const float4 self = h4_to_f4(__ldg(nh2 + (size_t)n * 32 + lane));
    float x1[4], x2[4];
    x1[0] = (accn.x + 2.f * self.x) * rd1;
    x1[1] = (accn.y + 2.f * self.y) * rd1;
    x1[2] = (accn.z + 2.f * self.z) * rd1;
    x1[3] = (accn.w + 2.f * self.w) * rd1;
    x2[0] = acce.x * rd2; x2[1] = acce.y * rd2;
    x2[2] = acce.z * rd2; x2[3] = acce.w * rd2;

    {
        uint2 a;
        a.x = hpair(x1[0], x1[1]);  a.y = hpair(x1[2], x1[3]);
        *reinterpret_cast<uint2*>(&h32[w][2 * lane]) = a;
        uint2 b;
        b.x = hpair(x2[0], x2[1]);  b.y = hpair(x2[2], x2[3]);
        *reinterpret_cast<uint2*>(&h32[w][64 + 2 * lane]) = b;
    }
    __syncthreads();

    {
        const int ks  = w;
        const int gid = lane >> 2;
        const int tig = lane & 3;
        uint4 vh;
        vh.x = h32[gid    ][ks * 8 + tig];
        vh.y = h32[gid + 8][ks * 8 + tig];
        vh.z = h32[gid    ][ks * 8 + 4 + tig];
        vh.w = h32[gid + 8][ks * 8 + 4 + tig];
        const size_t eidx = ((size_t)pan * 16 + ks) * 32 + lane;
        g_xh4[eidx] = vh;
    }
}

// ---------------------------------------------------------------------------
// fp16 HMMA GEMM, single pass. 256 threads = 8 warps.
// Block: 128 rows (8 panels) x 128 cols. Warp tile 32(M) x 64(N).
// ---------------------------------------------------------------------------
__global__ __launch_bounds__(256) void k_mgemm(const float* __restrict__ bn,
                                               const float* __restrict__ be,
                                               float* __restrict__ out) {
    const int bx   = blockIdx.x;
    const int tid  = threadIdx.x;
    const int w    = tid >> 5;
    const int lane = tid & 31;
    const int gid  = lane >> 2;
    const int tig  = lane & 3;
    const int warp_m = (w & 3) * 32;
    const int warp_n = (w >> 2) * 64;
    const int n0   = bx * 128;
    const int nppb = (w >> 2) * 4;

    float acc[2][8][4];
#pragma unroll
    for (int mt = 0; mt < 2; mt++)
#pragma unroll
        for (int nt = 0; nt < 8; nt++)
#pragma unroll
            for (int j = 0; j < 4; j++) acc[mt][nt][j] = 0.f;

    int  pan[2];
    bool pv[2];
#pragma unroll
    for (int mt = 0; mt < 2; mt++) {
        pan[mt] = bx * 8 + (w & 3) * 2 + mt;
        pv[mt]  = pan[mt] < N_PANELS;
    }

    const uint4* B4 = reinterpret_cast<const uint4*>(g_wh32);

    uint4 abuf[2][2];   // [buf][mt]
    auto loadA = [&](int ks, uint4* a_) {
#pragma unroll
        for (int mt = 0; mt < 2; mt++) {
            a_[mt] = make_uint4(0, 0, 0, 0);
            if (pv[mt])
                a_[mt] = __ldg(g_xh4 + ((size_t)(pan[mt] * 16 + ks) * 32 + lane));
        }
    };

    loadA(0, abuf[0]);

#pragma unroll 4
    for (int ks = 0; ks < 16; ks++) {
        const int buf = ks & 1;
        if (ks < 15) loadA(ks + 1, abuf[buf ^ 1]);   // overlap with mma

#pragma unroll
        for (int npq = 0; npq < 4; npq++) {
            const uint4 b4 = __ldg(B4 + (((size_t)(nppb + npq) * 16 + ks) * 32 + lane));
#pragma unroll
            for (int mt = 0; mt < 2; mt++) {
                const uint32_t* aF = reinterpret_cast<const uint32_t*>(&abuf[buf][mt]);
                mma_f16(acc[mt][npq * 2 + 0], aF, b4.x, b4.y);
                mma_f16(acc[mt][npq * 2 + 1], aF, b4.z, b4.w);
            }
        }
    }

    // ---- epilogue ----
#pragma unroll
    for (int mt = 0; mt < 2; mt++) {
        const int rA = n0 + warp_m + mt * 16 + gid;
        const int rB = rA + 8;
        const bool vA = rA < N_NODES;
        const bool vB = rB < N_NODES;
        float fA = 0.f, fB = 0.f;
        if (vA) fA = (__ldg(g_off + rA + 1) - __ldg(g_off + rA) > 0) ? 1.f : 0.f;
        if (vB) fB = (__ldg(g_off + rB + 1) - __ldg(g_off + rB) > 0) ? 1.f : 0.f;

#pragma unroll
        for (int nt = 0; nt < 8; nt++) {
            const int col = warp_n + nt * 8 + tig * 2;
            const float2 bnv = __ldg(reinterpret_cast<const float2*>(bn + col));
            const float2 bev = __ldg(reinterpret_cast<const float2*>(be + col));
            if (vA) {
                float2 o;
                o.x = acc[mt][nt][0] + bnv.x + fA * bev.x;
                o.y = acc[mt][nt][1] + bnv.y + fA * bev.y;
                *reinterpret_cast<float2*>(out + (size_t)rA * 128 + col) = o;
            }
            if (vB) {
                float2 o;
                o.x = acc[mt][nt][2] + bnv.x + fB * bev.x;
                o.y = acc[mt][nt][3] + bnv.y + fB * bev.y;
                *reinterpret_cast<float2*>(out + (size_t)rB * 128 + col) = o;
            }
        }
    }
}

// ---------------------------------------------------------------------------
extern "C" void kernel_launch(void* const* d_in, const int* in_sizes, int n_in,
                              void* d_out, int out_size) {
    const float* nfeat = (const float*)d_in[0];
    const float* efeat = (const float*)d_in[1];
    const float* ew    = (const float*)d_in[2];
    const float* Wn    = (const float*)d_in[3];
    const float* bn    = (const float*)d_in[4];
    const float* We    = (const float*)d_in[5];
    const float* be    = (const float*)d_in[6];
    const int*   src   = (const int*)d_in[7];
    const int*   dst   = (const int*)d_in[8];
    float*       out   = (float*)d_out;

    (void)in_sizes; (void)n_in; (void)out_size;

    k_nsplit<<<(N_NODES * 32 + 255) / 256, 256>>>(nfeat);   // zero + nfeat->fp16
    k_wsplit<<<64, 256>>>(Wn, We);
    k_hist  <<<(N_EDGES + 255) / 256, 256>>>(dst);
    k_scan1 <<<N_SCAN_BLOCKS, SCAN_BLK>>>();
    k_scan2 <<<1, 128>>>();
    k_scan3 <<<(N_NODES + 255) / 256, 256>>>();
    k_perm  <<<(N_EDGES + 255) / 256, 256>>>(src, dst, ew);
    k_gather<<<N_PANELS, 512>>>(efeat);
    k_mgemm <<<(N_NODES + 127) / 128, 256>>>(bn, be, out);
}